// round 9
// baseline (speedup 1.0000x reference)
#include <cuda_runtime.h>
#include <math.h>
#include <stdint.h>

// ---------------------------------------------------------------------------
// Problem constants
// ---------------------------------------------------------------------------
#define NSAMP  8192
#define NDIMT  3072
#define NKER   64
#define NSUB   48
#define MKNOT  200
#define NTRT   3072

// ---------------------------------------------------------------------------
// Device scratch (static only)
// ---------------------------------------------------------------------------
__device__ float g_Q  [NKER * NSUB * NSUB];   // [k][j][i]
__device__ float g_QT [NKER * NSUB * NSUB];   // [k][i][j]
__device__ float g_xx [NTRT * MKNOT];
__device__ float g_yy [NTRT * MKNOT];
__device__ float g_dl [NTRT * MKNOT];
__device__ float g_lj [NKER * NSAMP];
__device__ unsigned char g_lut[NTRT * 256];
__device__ float g_lxlo[NTRT];
__device__ float g_livw[NTRT];

// ---------------------------------------------------------------------------
// f32x2 helpers (packed fp32 — exact fp32 per lane)
// ---------------------------------------------------------------------------
__device__ __forceinline__ void ffma2(unsigned long long& acc,
                                      unsigned long long a, unsigned long long b) {
    asm("fma.rn.f32x2 %0, %1, %2, %0;" : "+l"(acc) : "l"(a), "l"(b));
}
__device__ __forceinline__ unsigned long long splat2(float v) {
    unsigned long long r;
    asm("mov.b64 %0, {%1, %1};" : "=l"(r) : "f"(v));
    return r;
}
__device__ __forceinline__ float2 unpk2(unsigned long long v) {
    float2 r;
    asm("mov.b64 {%0, %1}, %2;" : "=f"(r.x), "=f"(r.y) : "l"(v));
    return r;
}

// ---------------------------------------------------------------------------
// Kernel 1: per-patch MGS QR (positive diagonal), writes Q and Q^T.
// ---------------------------------------------------------------------------
__global__ void orth_kernel(const float* __restrict__ A_raw) {
    const int k   = blockIdx.x;
    const int tid = threadIdx.x;
    __shared__ float qcol[NSUB];

    float col[NSUB];
    const float* Ab = A_raw + k * (NSUB * NSUB);
    if (tid < NSUB) {
#pragma unroll
        for (int r = 0; r < NSUB; ++r) col[r] = Ab[r * NSUB + tid];
    }

    for (int c = 0; c < NSUB; ++c) {
        if (tid == c) {
            float nrm = 0.f;
#pragma unroll
            for (int r = 0; r < NSUB; ++r) nrm += col[r] * col[r];
            float inv = 1.0f / sqrtf(nrm);
#pragma unroll
            for (int r = 0; r < NSUB; ++r) { col[r] *= inv; qcol[r] = col[r]; }
        }
        __syncthreads();
        if (tid < NSUB) {
            if (tid == c) {
                float* gq  = g_Q  + k * (NSUB * NSUB);
                float* gqt = g_QT + k * (NSUB * NSUB);
#pragma unroll
                for (int r = 0; r < NSUB; ++r) {
                    gq [r * NSUB + c] = qcol[r];
                    gqt[c * NSUB + r] = qcol[r];
                }
            } else if (tid > c) {
                float dot = 0.f;
#pragma unroll
                for (int r = 0; r < NSUB; ++r) dot += qcol[r] * col[r];
#pragma unroll
                for (int r = 0; r < NSUB; ++r) col[r] -= dot * qcol[r];
            }
        }
        __syncthreads();
    }
}

// ---------------------------------------------------------------------------
// Kernel 2: knot tables via warp scans.
// ---------------------------------------------------------------------------
__global__ void knots_kernel(const float* __restrict__ x0,
                             const float* __restrict__ logdx,
                             const float* __restrict__ y0,
                             const float* __restrict__ logdy,
                             const float* __restrict__ logderiv) {
    const int warp = (blockIdx.x * blockDim.x + threadIdx.x) >> 5;
    const int lane = threadIdx.x & 31;
    if (warp >= NTRT) return;

    {
        float carry = x0[warp];
        if (lane == 0) g_xx[warp * MKNOT] = carry;
        const float* src = logdx + (size_t)warp * (MKNOT - 1);
        for (int c = 0; c < MKNOT - 1; c += 32) {
            int m = c + lane;
            float v = (m < MKNOT - 1) ? expf(src[m]) : 0.f;
#pragma unroll
            for (int off = 1; off < 32; off <<= 1) {
                float o = __shfl_up_sync(0xffffffffu, v, off);
                if (lane >= off) v += o;
            }
            if (m < MKNOT - 1) g_xx[warp * MKNOT + m + 1] = carry + v;
            carry += __shfl_sync(0xffffffffu, v, 31);
        }
    }
    {
        float carry = y0[warp];
        if (lane == 0) g_yy[warp * MKNOT] = carry;
        const float* src = logdy + (size_t)warp * (MKNOT - 1);
        for (int c = 0; c < MKNOT - 1; c += 32) {
            int m = c + lane;
            float v = (m < MKNOT - 1) ? expf(src[m]) : 0.f;
#pragma unroll
            for (int off = 1; off < 32; off <<= 1) {
                float o = __shfl_up_sync(0xffffffffu, v, off);
                if (lane >= off) v += o;
            }
            if (m < MKNOT - 1) g_yy[warp * MKNOT + m + 1] = carry + v;
            carry += __shfl_sync(0xffffffffu, v, 31);
        }
    }
    for (int m = lane; m < MKNOT; m += 32)
        g_dl[warp * MKNOT + m] = expf(logderiv[(size_t)warp * MKNOT + m]);
}

// ---------------------------------------------------------------------------
// Kernel 2b: per-coordinate 256-bin search LUT.
// ---------------------------------------------------------------------------
__global__ void lut_kernel() {
    const int warp = (blockIdx.x * blockDim.x + threadIdx.x) >> 5;
    const int lane = threadIdx.x & 31;
    if (warp >= NTRT) return;
    const float* xr = g_xx + (size_t)warp * MKNOT;
    float xlo = xr[0], xhi = xr[MKNOT - 1];
    float binw = (xhi - xlo) * (1.0f / 256.0f);
    if (lane == 0) { g_lxlo[warp] = xlo; g_livw[warp] = 256.0f / (xhi - xlo); }
#pragma unroll
    for (int t = 0; t < 8; ++t) {
        int q = lane + 32 * t;
        float L = xlo + q * binw;
        int lo = 0, hi = MKNOT;
        while (lo < hi) { int mid = (lo + hi) >> 1; if (xr[mid] < L) lo = mid + 1; else hi = mid; }
        g_lut[(size_t)warp * 256 + q] = (unsigned char)lo;
    }
}

// ---------------------------------------------------------------------------
// Kernel 3: fused pipeline. 1024 threads, 32 warps, 1 CTA/SM.
// ---------------------------------------------------------------------------
#define TPB      1024
#define ROWS_IT  128
#define ITERS    4
#define RST      130
#define GELEM    (NSUB * ROWS_IT)      // 6144 staged elements
#define GPT      (GELEM / TPB)         // 6 per thread

// smem layout (float offsets)
#define SO_X   0                        // 48*200 x-knots
#define SO_YD  (SO_X + 48*200)          // 48*200 float2 {y,d}
#define SO_Q   (SO_YD + 48*200*2)       // [j][i]
#define SO_QT  (SO_Q  + 48*48)          // [i][j]
#define SO_V   (SO_QT + 48*48)          // gather buffer (becomes V+W)
#define SO_S   (SO_V  + 48*RST)         // spline output
#define SO_LJ  (SO_S  + 48*RST)         // [8][128]
#define SO_XLO (SO_LJ + 8*128)
#define SO_IVW (SO_XLO + 48)
#define SO_RI  (SO_IVW + 48)
#define SO_LUT (SO_RI + 48)             // uint8[12288]
#define SMEM_FLOATS (SO_LUT + 3072)
#define SMEM_BYTES  (SMEM_FLOATS * 4)   // 200,512 B

__device__ __forceinline__ float rq_eval(float x,
                                         const float* __restrict__ xr,
                                         const float2* __restrict__ yd,
                                         const unsigned char* __restrict__ lut,
                                         float xlo, float ivw, float& dv) {
    int q = __float2int_rd((x - xlo) * ivw);
    q = min(max(q, 0), 255);
    int idx = lut[q];
    while (idx > 0 && xr[idx - 1] >= x) --idx;
    while (idx < MKNOT && xr[idx] < x) ++idx;
    if (idx == 0) {
        float2 k0 = yd[0];
        dv = k0.y;
        return k0.x + dv * (x - xr[0]);
    }
    if (idx == MKNOT) {
        float2 km = yd[MKNOT - 1];
        dv = km.y;
        return km.x + dv * (x - xr[MKNOT - 1]);
    }
    const int kk = idx - 1;
    const float  xK = xr[kk], xK1 = xr[kk + 1];
    const float2 k0 = yd[kk], k1 = yd[kk + 1];
    const float inv = __fdividef(1.f, xK1 - xK);
    float xi = fminf(fmaxf((x - xK) * inv, 0.f), 1.f);
    const float sl  = (k1.x - k0.x) * inv;
    const float xi1 = xi * (1.f - xi);
    const float den = sl + (k1.y + k0.y - 2.f * sl) * xi1;
    const float ivd = __fdividef(1.f, den);
    const float om  = 1.f - xi;
    dv = sl * sl * (k1.y * xi * xi + 2.f * sl * xi1 + k0.y * om * om) * ivd * ivd;
    return k0.x + (k1.x - k0.x) * (sl * xi * xi + k0.y * xi1) * ivd;
}

__global__ void __launch_bounds__(TPB, 1)
fused_kernel(const float* __restrict__ data, float* __restrict__ out) {
    extern __shared__ float sm[];
    int* ri = (int*)&sm[SO_RI];
    unsigned char* slut = (unsigned char*)&sm[SO_LUT];

    const int tid = threadIdx.x;
    const int k   = blockIdx.x;

    // ---- prologue --------------------------------------------------------
    {
        const float4* gq  = (const float4*)(g_Q  + k * (NSUB * NSUB));
        const float4* gqt = (const float4*)(g_QT + k * (NSUB * NSUB));
        float4* sq  = (float4*)&sm[SO_Q];
        float4* sqt = (float4*)&sm[SO_QT];
        for (int idx = tid; idx < NSUB * NSUB / 4; idx += TPB) {
            sq[idx]  = gq[idx];
            sqt[idx] = gqt[idx];
        }
        const float4* gx = (const float4*)(g_xx + (size_t)k * NSUB * MKNOT);
        float4* sx = (float4*)&sm[SO_X];
        for (int idx = tid; idx < NSUB * MKNOT / 4; idx += TPB) sx[idx] = gx[idx];
        const float* gy = g_yy + (size_t)k * NSUB * MKNOT;
        const float* gd = g_dl + (size_t)k * NSUB * MKNOT;
        float2* syd = (float2*)&sm[SO_YD];
        for (int idx = tid; idx < NSUB * MKNOT; idx += TPB) {
            float2 v; v.x = gy[idx]; v.y = gd[idx];
            syd[idx] = v;
        }
        const int4* gl = (const int4*)(g_lut + (size_t)k * NSUB * 256);
        int4* sl = (int4*)slut;
        for (int idx = tid; idx < NSUB * 256 / 16; idx += TPB) sl[idx] = gl[idx];
        if (tid < NSUB) {
            sm[SO_XLO + tid] = g_lxlo[k * NSUB + tid];
            sm[SO_IVW + tid] = g_livw[k * NSUB + tid];
            int nh = k >> 3, nw = k & 7;
            int kh = tid / 12, rem = tid - kh * 12, kw = rem / 3, c = rem - kw * 3;
            int h = (nh * 4 + kh + 2) & 31;
            int w = (nw * 4 + kw + 2) & 31;
            ri[tid] = h * 96 + w * 3 + c;
        }
    }
    __syncthreads();

    // staging map: element e = r*48 + j  (j fast -> coalesced-ish gathers)
    unsigned int ge_r[GPT];
    int          ge_a[GPT];             // gmem offset within a row-block
#pragma unroll
    for (int t = 0; t < GPT; ++t) {
        unsigned int e = tid + TPB * t;
        unsigned int r = e / 48u;
        unsigned int j = e - r * 48u;
        ge_r[t] = r;
        ge_a[t] = (int)r * NDIMT + ri[j];
    }

    const int ig = tid >> 7;          // 0..7 : i/j tile group (6 wide)
    const int rr = tid & 127;         // row
    const int i0 = ig * 6;
    const int nb0 = blockIdx.y * (ROWS_IT * ITERS);

    // prefetch iteration 0
    float pf[GPT];
#pragma unroll
    for (int t = 0; t < GPT; ++t)
        pf[t] = __ldg(&data[(size_t)nb0 * NDIMT + ge_a[t]]);

    for (int it = 0; it < ITERS; ++it) {
        const int nbase = nb0 + it * ROWS_IT;

        // ---- stage V from prefetch regs ----------------------------------
        __syncthreads();               // V free (previous scatter done)
#pragma unroll
        for (int t = 0; t < GPT; ++t) {
            unsigned int e = tid + TPB * t;
            unsigned int r = ge_r[t];
            unsigned int j = e - r * 48u;
            sm[SO_V + j * RST + r] = pf[t];
        }
        __syncthreads();

        // ---- prefetch next iter (hidden behind GEMV + spline) -------------
        if (it + 1 < ITERS) {
            const float* base = &data[(size_t)(nbase + ROWS_IT) * NDIMT];
#pragma unroll
            for (int t = 0; t < GPT; ++t) pf[t] = __ldg(&base[ge_a[t]]);
        }

        // ---- fwd GEMV (U in regs) + fused RQ spline -> S, logdet ----------
        {
            unsigned long long a0 = 0, a1 = 0, a2 = 0;
#pragma unroll 8
            for (int j = 0; j < 48; ++j) {
                const float v = sm[SO_V + j * RST + rr];
                const unsigned long long vv = splat2(v);
                const unsigned long long q0 = *(const unsigned long long*)&sm[SO_Q + j * 48 + i0];
                const unsigned long long q1 = *(const unsigned long long*)&sm[SO_Q + j * 48 + i0 + 2];
                const unsigned long long q2 = *(const unsigned long long*)&sm[SO_Q + j * 48 + i0 + 4];
                ffma2(a0, q0, vv);
                ffma2(a1, q1, vv);
                ffma2(a2, q2, vv);
            }
            float u[6];
            { float2 f = unpk2(a0); u[0] = f.x; u[1] = f.y; }
            { float2 f = unpk2(a1); u[2] = f.x; u[3] = f.y; }
            { float2 f = unpk2(a2); u[4] = f.x; u[5] = f.y; }

            float p = 1.f;
#pragma unroll
            for (int s = 0; s < 6; ++s) {
                const int i = i0 + s;
                const float*  xr = &sm[SO_X + i * MKNOT];
                const float2* yd = (const float2*)&sm[SO_YD + (i * MKNOT) * 2];
                const unsigned char* lut = slut + i * 256;
                const float xlo = sm[SO_XLO + i];
                const float ivw = sm[SO_IVW + i];
                float dv;
                float yv = rq_eval(u[s], xr, yd, lut, xlo, ivw, dv);
                sm[SO_S + i * RST + rr] = yv - u[s];
                p *= dv;
            }
            sm[SO_LJ + ig * 128 + rr] = __logf(p);
        }
        __syncthreads();

        // ---- bwd GEMV: W[j][r] = sum_i QT[i][j]*S[i][r]; V += W in place --
        {
            unsigned long long a0 = 0, a1 = 0, a2 = 0;
            const int j0 = i0;
#pragma unroll 8
            for (int i = 0; i < 48; ++i) {
                const float v = sm[SO_S + i * RST + rr];
                const unsigned long long vv = splat2(v);
                const unsigned long long q0 = *(const unsigned long long*)&sm[SO_QT + i * 48 + j0];
                const unsigned long long q1 = *(const unsigned long long*)&sm[SO_QT + i * 48 + j0 + 2];
                const unsigned long long q2 = *(const unsigned long long*)&sm[SO_QT + i * 48 + j0 + 4];
                ffma2(a0, q0, vv);
                ffma2(a1, q1, vv);
                ffma2(a2, q2, vv);
            }
            float w[6];
            { float2 f = unpk2(a0); w[0] = f.x; w[1] = f.y; }
            { float2 f = unpk2(a1); w[2] = f.x; w[3] = f.y; }
            { float2 f = unpk2(a2); w[4] = f.x; w[5] = f.y; }
#pragma unroll
            for (int p = 0; p < 6; ++p)
                sm[SO_V + (j0 + p) * RST + rr] += w[p];   // exclusive (j,r)
        }
        __syncthreads();

        // ---- scatter (V holds V+W) + per-row logdet partials --------------
        {
            float* obase = &out[(size_t)nbase * NDIMT];
#pragma unroll
            for (int t = 0; t < GPT; ++t) {
                unsigned int e = tid + TPB * t;
                unsigned int r = ge_r[t];
                unsigned int j = e - r * 48u;
                obase[ge_a[t]] = sm[SO_V + j * RST + r];
            }
            if (tid < ROWS_IT) {
                float s = 0.f;
#pragma unroll
                for (int g = 0; g < 8; ++g) s += sm[SO_LJ + g * 128 + tid];
                g_lj[(size_t)k * NSAMP + nbase + tid] = s;
            }
        }
    }
}

// ---------------------------------------------------------------------------
// Kernel 4: deterministic logdet reduction.
// ---------------------------------------------------------------------------
__global__ void reduce_lj(float* __restrict__ logj) {
    int n = blockIdx.x * blockDim.x + threadIdx.x;
    if (n >= NSAMP) return;
    float s = 0.f;
#pragma unroll
    for (int k = 0; k < NKER; ++k) s += g_lj[(size_t)k * NSAMP + n];
    logj[n] = s;
}

// ---------------------------------------------------------------------------
// Launch
// ---------------------------------------------------------------------------
extern "C" void kernel_launch(void* const* d_in, const int* in_sizes, int n_in,
                              void* d_out, int out_size) {
    const float* data     = (const float*)d_in[0];
    const float* A_raw    = (const float*)d_in[1];
    const float* x0       = (const float*)d_in[2];
    const float* logdx    = (const float*)d_in[3];
    const float* y0       = (const float*)d_in[4];
    const float* logdy    = (const float*)d_in[5];
    const float* logderiv = (const float*)d_in[6];

    float* out  = (float*)d_out;
    float* logj = out + (size_t)NSAMP * NDIMT;

    cudaFuncSetAttribute(fused_kernel,
                         cudaFuncAttributeMaxDynamicSharedMemorySize, SMEM_BYTES);

    orth_kernel<<<NKER, 64>>>(A_raw);
    knots_kernel<<<NTRT / 4, 128>>>(x0, logdx, y0, logdy, logderiv);
    lut_kernel<<<NTRT / 8, 256>>>();
    fused_kernel<<<dim3(NKER, 16), TPB, SMEM_BYTES>>>(data, out);
    reduce_lj<<<(NSAMP + 255) / 256, 256>>>(logj);
}

// round 10
// speedup vs baseline: 1.1134x; 1.1134x over previous
#include <cuda_runtime.h>
#include <math.h>
#include <stdint.h>

// ---------------------------------------------------------------------------
// Problem constants
// ---------------------------------------------------------------------------
#define NSAMP  8192
#define NDIMT  3072
#define NKER   64
#define NSUB   48
#define MKNOT  200
#define NTRT   3072

// ---------------------------------------------------------------------------
// Device scratch (static only)
// ---------------------------------------------------------------------------
__device__ float  g_Q  [NKER * NSUB * NSUB];   // [k][j][i]
__device__ float  g_QT [NKER * NSUB * NSUB];   // [k][i][j]
__device__ float  g_xx [NTRT * MKNOT];         // x knots
__device__ float2 g_yd [NTRT * MKNOT];         // (y, d) knots, interleaved
__device__ float  g_lj [NKER * NSAMP];
__device__ unsigned char g_lut[NTRT * 256];
__device__ float  g_lxlo[NTRT];
__device__ float  g_livw[NTRT];

// ---------------------------------------------------------------------------
// f32x2 helpers (packed fp32 — exact fp32 per lane)
// ---------------------------------------------------------------------------
__device__ __forceinline__ void ffma2(unsigned long long& acc,
                                      unsigned long long a, unsigned long long b) {
    asm("fma.rn.f32x2 %0, %1, %2, %0;" : "+l"(acc) : "l"(a), "l"(b));
}
__device__ __forceinline__ unsigned long long splat2(float v) {
    unsigned long long r;
    asm("mov.b64 %0, {%1, %1};" : "=l"(r) : "f"(v));
    return r;
}
__device__ __forceinline__ float2 unpk2(unsigned long long v) {
    float2 r;
    asm("mov.b64 {%0, %1}, %2;" : "=f"(r.x), "=f"(r.y) : "l"(v));
    return r;
}

// ---------------------------------------------------------------------------
// Kernel 1: per-patch MGS QR (positive diagonal), writes Q and Q^T.
// ---------------------------------------------------------------------------
__global__ void orth_kernel(const float* __restrict__ A_raw) {
    const int k   = blockIdx.x;
    const int tid = threadIdx.x;
    __shared__ float qcol[NSUB];

    float col[NSUB];
    const float* Ab = A_raw + k * (NSUB * NSUB);
    if (tid < NSUB) {
#pragma unroll
        for (int r = 0; r < NSUB; ++r) col[r] = Ab[r * NSUB + tid];
    }

    for (int c = 0; c < NSUB; ++c) {
        if (tid == c) {
            float nrm = 0.f;
#pragma unroll
            for (int r = 0; r < NSUB; ++r) nrm += col[r] * col[r];
            float inv = 1.0f / sqrtf(nrm);
#pragma unroll
            for (int r = 0; r < NSUB; ++r) { col[r] *= inv; qcol[r] = col[r]; }
        }
        __syncthreads();
        if (tid < NSUB) {
            if (tid == c) {
                float* gq  = g_Q  + k * (NSUB * NSUB);
                float* gqt = g_QT + k * (NSUB * NSUB);
#pragma unroll
                for (int r = 0; r < NSUB; ++r) {
                    gq [r * NSUB + c] = qcol[r];
                    gqt[c * NSUB + r] = qcol[r];
                }
            } else if (tid > c) {
                float dot = 0.f;
#pragma unroll
                for (int r = 0; r < NSUB; ++r) dot += qcol[r] * col[r];
#pragma unroll
                for (int r = 0; r < NSUB; ++r) col[r] -= dot * qcol[r];
            }
        }
        __syncthreads();
    }
}

// ---------------------------------------------------------------------------
// Kernel 2: knot tables via warp scans. y/d written interleaved into g_yd.
// ---------------------------------------------------------------------------
__global__ void knots_kernel(const float* __restrict__ x0,
                             const float* __restrict__ logdx,
                             const float* __restrict__ y0,
                             const float* __restrict__ logdy,
                             const float* __restrict__ logderiv) {
    const int warp = (blockIdx.x * blockDim.x + threadIdx.x) >> 5;
    const int lane = threadIdx.x & 31;
    if (warp >= NTRT) return;

    {
        float carry = x0[warp];
        if (lane == 0) g_xx[warp * MKNOT] = carry;
        const float* src = logdx + (size_t)warp * (MKNOT - 1);
        for (int c = 0; c < MKNOT - 1; c += 32) {
            int m = c + lane;
            float v = (m < MKNOT - 1) ? expf(src[m]) : 0.f;
#pragma unroll
            for (int off = 1; off < 32; off <<= 1) {
                float o = __shfl_up_sync(0xffffffffu, v, off);
                if (lane >= off) v += o;
            }
            if (m < MKNOT - 1) g_xx[warp * MKNOT + m + 1] = carry + v;
            carry += __shfl_sync(0xffffffffu, v, 31);
        }
    }
    {
        float carry = y0[warp];
        if (lane == 0) g_yd[warp * MKNOT].x = carry;
        const float* src = logdy + (size_t)warp * (MKNOT - 1);
        for (int c = 0; c < MKNOT - 1; c += 32) {
            int m = c + lane;
            float v = (m < MKNOT - 1) ? expf(src[m]) : 0.f;
#pragma unroll
            for (int off = 1; off < 32; off <<= 1) {
                float o = __shfl_up_sync(0xffffffffu, v, off);
                if (lane >= off) v += o;
            }
            if (m < MKNOT - 1) g_yd[warp * MKNOT + m + 1].x = carry + v;
            carry += __shfl_sync(0xffffffffu, v, 31);
        }
    }
    for (int m = lane; m < MKNOT; m += 32)
        g_yd[warp * MKNOT + m].y = expf(logderiv[(size_t)warp * MKNOT + m]);
}

// ---------------------------------------------------------------------------
// Kernel 2b: per-coordinate 256-bin search LUT.
// ---------------------------------------------------------------------------
__global__ void lut_kernel() {
    const int warp = (blockIdx.x * blockDim.x + threadIdx.x) >> 5;
    const int lane = threadIdx.x & 31;
    if (warp >= NTRT) return;
    const float* xr = g_xx + (size_t)warp * MKNOT;
    float xlo = xr[0], xhi = xr[MKNOT - 1];
    float binw = (xhi - xlo) * (1.0f / 256.0f);
    if (lane == 0) { g_lxlo[warp] = xlo; g_livw[warp] = 256.0f / (xhi - xlo); }
#pragma unroll
    for (int t = 0; t < 8; ++t) {
        int q = lane + 32 * t;
        float L = xlo + q * binw;
        int lo = 0, hi = MKNOT;
        while (lo < hi) { int mid = (lo + hi) >> 1; if (xr[mid] < L) lo = mid + 1; else hi = mid; }
        g_lut[(size_t)warp * 256 + q] = (unsigned char)lo;
    }
}

// ---------------------------------------------------------------------------
// Kernel 3: fused pipeline. 768 threads, i4 x r4 register tiles, 256 rows/iter.
// ---------------------------------------------------------------------------
#define TPB      768
#define ROWS_IT  256
#define ITERS    2
#define RST      260                    // padded row stride (260 % 4 == 0)
#define GELEM    (NSUB * ROWS_IT)       // 12288 staged elements
#define GPT      (GELEM / TPB)          // 16 per thread

// smem layout (float offsets, all float4-aligned)
#define SO_X   0                        // 48*200 x-knots
#define SO_Q   (SO_X + 48*200)          // 9600 : [j][i]
#define SO_QT  (SO_Q  + 48*48)          // 11904 : [i][j]
#define SO_V   (SO_QT + 48*48)          // 14208 : gather buffer (becomes V+W)
#define SO_S   (SO_V  + 48*RST)         // 26688 : spline output
#define SO_LJ  (SO_S  + 48*RST)         // 39168 : [12][256]
#define SO_XLO (SO_LJ + 12*256)         // 42240
#define SO_IVW (SO_XLO + 48)            // 42288
#define SO_RI  (SO_IVW + 48)            // 42336
#define SO_LUT (SO_RI + 48)             // 42384 : uint8[12288]
#define SMEM_FLOATS (SO_LUT + 3072)     // 45456
#define SMEM_BYTES  (SMEM_FLOATS * 4)   // 181,824 B

__device__ __forceinline__ float rq_eval(float x,
                                         const float* __restrict__ xr,
                                         const float2* __restrict__ yd,   // global (L2)
                                         const unsigned char* __restrict__ lut,
                                         float xlo, float ivw, float& dv) {
    int q = __float2int_rd((x - xlo) * ivw);
    q = min(max(q, 0), 255);
    int idx = lut[q];
    while (idx > 0 && xr[idx - 1] >= x) --idx;
    while (idx < MKNOT && xr[idx] < x) ++idx;
    if (idx == 0) {
        float2 k0 = __ldg(&yd[0]);
        dv = k0.y;
        return k0.x + dv * (x - xr[0]);
    }
    if (idx == MKNOT) {
        float2 km = __ldg(&yd[MKNOT - 1]);
        dv = km.y;
        return km.x + dv * (x - xr[MKNOT - 1]);
    }
    const int kk = idx - 1;
    const float  xK = xr[kk], xK1 = xr[kk + 1];
    const float2 k0 = __ldg(&yd[kk]);
    const float2 k1 = __ldg(&yd[kk + 1]);
    const float inv = __fdividef(1.f, xK1 - xK);
    float xi = fminf(fmaxf((x - xK) * inv, 0.f), 1.f);
    const float sl  = (k1.x - k0.x) * inv;
    const float xi1 = xi * (1.f - xi);
    const float den = sl + (k1.y + k0.y - 2.f * sl) * xi1;
    const float ivd = __fdividef(1.f, den);
    const float om  = 1.f - xi;
    dv = sl * sl * (k1.y * xi * xi + 2.f * sl * xi1 + k0.y * om * om) * ivd * ivd;
    return k0.x + (k1.x - k0.x) * (sl * xi * xi + k0.y * xi1) * ivd;
}

__global__ void __launch_bounds__(TPB, 1)
fused_kernel(const float* __restrict__ data, float* __restrict__ out) {
    extern __shared__ float sm[];
    int* ri = (int*)&sm[SO_RI];
    unsigned char* slut = (unsigned char*)&sm[SO_LUT];

    const int tid = threadIdx.x;
    const int k   = blockIdx.x;

    // ---- prologue --------------------------------------------------------
    {
        const float4* gq  = (const float4*)(g_Q  + k * (NSUB * NSUB));
        const float4* gqt = (const float4*)(g_QT + k * (NSUB * NSUB));
        float4* sq  = (float4*)&sm[SO_Q];
        float4* sqt = (float4*)&sm[SO_QT];
        for (int idx = tid; idx < NSUB * NSUB / 4; idx += TPB) {
            sq[idx]  = gq[idx];
            sqt[idx] = gqt[idx];
        }
        const float4* gx = (const float4*)(g_xx + (size_t)k * NSUB * MKNOT);
        float4* sx = (float4*)&sm[SO_X];
        for (int idx = tid; idx < NSUB * MKNOT / 4; idx += TPB) sx[idx] = gx[idx];
        const int4* gl = (const int4*)(g_lut + (size_t)k * NSUB * 256);
        int4* sl = (int4*)slut;
        for (int idx = tid; idx < NSUB * 256 / 16; idx += TPB) sl[idx] = gl[idx];
        if (tid < NSUB) {
            sm[SO_XLO + tid] = g_lxlo[k * NSUB + tid];
            sm[SO_IVW + tid] = g_livw[k * NSUB + tid];
            int nh = k >> 3, nw = k & 7;
            int kh = tid / 12, rem = tid - kh * 12, kw = rem / 3, c = rem - kw * 3;
            int h = (nh * 4 + kh + 2) & 31;
            int w = (nw * 4 + kw + 2) & 31;
            ri[tid] = h * 96 + w * 3 + c;
        }
    }
    __syncthreads();

    // staging map: element e = r*48 + j
    unsigned int ge_r[GPT];
    int          ge_a[GPT];
#pragma unroll
    for (int t = 0; t < GPT; ++t) {
        unsigned int e = tid + TPB * t;
        unsigned int r = e / 48u;
        unsigned int j = e - r * 48u;
        ge_r[t] = r;
        ge_a[t] = (int)r * NDIMT + ri[j];
    }

    const int ig = tid >> 6;            // 0..11 : i/j tile group (4 wide)
    const int rg = tid & 63;            // 0..63 : r tile group (4 wide)
    const int i0 = ig * 4;
    const int r0 = rg * 4;
    const int nb0 = blockIdx.y * (ROWS_IT * ITERS);
    const float2* ydk = g_yd + (size_t)k * NSUB * MKNOT;

    // prefetch iteration 0
    float pf[GPT];
#pragma unroll
    for (int t = 0; t < GPT; ++t)
        pf[t] = __ldg(&data[(size_t)nb0 * NDIMT + ge_a[t]]);

    for (int it = 0; it < ITERS; ++it) {
        const int nbase = nb0 + it * ROWS_IT;

        // ---- stage V from prefetch regs -----------------------------------
        __syncthreads();                 // previous scatter done; V free
#pragma unroll
        for (int t = 0; t < GPT; ++t) {
            unsigned int e = tid + TPB * t;
            unsigned int r = ge_r[t];
            unsigned int j = e - r * 48u;
            sm[SO_V + j * RST + r] = pf[t];
        }
        __syncthreads();

        // ---- prefetch next iter (hidden behind GEMV + spline) -------------
        if (it + 1 < ITERS) {
            const float* base = &data[(size_t)(nbase + ROWS_IT) * NDIMT];
#pragma unroll
            for (int t = 0; t < GPT; ++t) pf[t] = __ldg(&base[ge_a[t]]);
        }

        // ---- fwd GEMV (i4 x r4, U in regs) + fused RQ spline ---------------
        {
            unsigned long long acc[4][2] = {{0,0},{0,0},{0,0},{0,0}};
#pragma unroll 6
            for (int j = 0; j < 48; ++j) {
                const float4 q = *(const float4*)&sm[SO_Q + j * 48 + i0];       // bcast
                const ulonglong2 v = *(const ulonglong2*)&sm[SO_V + j * RST + r0];
                const unsigned long long q0 = splat2(q.x), q1 = splat2(q.y);
                const unsigned long long q2 = splat2(q.z), q3 = splat2(q.w);
                ffma2(acc[0][0], q0, v.x); ffma2(acc[0][1], q0, v.y);
                ffma2(acc[1][0], q1, v.x); ffma2(acc[1][1], q1, v.y);
                ffma2(acc[2][0], q2, v.x); ffma2(acc[2][1], q2, v.y);
                ffma2(acc[3][0], q3, v.x); ffma2(acc[3][1], q3, v.y);
            }
            float lj[4] = {0.f, 0.f, 0.f, 0.f};
#pragma unroll
            for (int s = 0; s < 4; ++s) {
                const int i = i0 + s;
                const float*  xr = &sm[SO_X + i * MKNOT];
                const float2* yd = ydk + i * MKNOT;
                const unsigned char* lut = slut + i * 256;
                const float xlo = sm[SO_XLO + i];
                const float ivw = sm[SO_IVW + i];

                float2 ua = unpk2(acc[s][0]);
                float2 ub = unpk2(acc[s][1]);
                float u[4] = {ua.x, ua.y, ub.x, ub.y};
                float4 sv;
                float d0, d1, d2, d3;
                sv.x = rq_eval(u[0], xr, yd, lut, xlo, ivw, d0) - u[0];
                sv.y = rq_eval(u[1], xr, yd, lut, xlo, ivw, d1) - u[1];
                sv.z = rq_eval(u[2], xr, yd, lut, xlo, ivw, d2) - u[2];
                sv.w = rq_eval(u[3], xr, yd, lut, xlo, ivw, d3) - u[3];
                *(float4*)&sm[SO_S + i * RST + r0] = sv;
                lj[0] += __logf(d0); lj[1] += __logf(d1);
                lj[2] += __logf(d2); lj[3] += __logf(d3);
            }
            float4 lj4; lj4.x = lj[0]; lj4.y = lj[1]; lj4.z = lj[2]; lj4.w = lj[3];
            *(float4*)&sm[SO_LJ + ig * 256 + r0] = lj4;
        }
        __syncthreads();

        // ---- bwd GEMV: W[j][r] = sum_i QT[i][j]*S[i][r]; V += W in place ---
        {
            unsigned long long acc[4][2] = {{0,0},{0,0},{0,0},{0,0}};
            const int j0 = i0;
#pragma unroll 6
            for (int i = 0; i < 48; ++i) {
                const float4 q = *(const float4*)&sm[SO_QT + i * 48 + j0];      // bcast
                const ulonglong2 v = *(const ulonglong2*)&sm[SO_S + i * RST + r0];
                const unsigned long long q0 = splat2(q.x), q1 = splat2(q.y);
                const unsigned long long q2 = splat2(q.z), q3 = splat2(q.w);
                ffma2(acc[0][0], q0, v.x); ffma2(acc[0][1], q0, v.y);
                ffma2(acc[1][0], q1, v.x); ffma2(acc[1][1], q1, v.y);
                ffma2(acc[2][0], q2, v.x); ffma2(acc[2][1], q2, v.y);
                ffma2(acc[3][0], q3, v.x); ffma2(acc[3][1], q3, v.y);
            }
#pragma unroll
            for (int p = 0; p < 4; ++p) {
                float4* vp = (float4*)&sm[SO_V + (j0 + p) * RST + r0];
                float4 v = *vp;                                   // exclusive tile
                float2 wa = unpk2(acc[p][0]);
                float2 wb = unpk2(acc[p][1]);
                v.x += wa.x; v.y += wa.y; v.z += wb.x; v.w += wb.y;
                *vp = v;
            }
        }
        __syncthreads();

        // ---- scatter (V holds V+W) + per-row logdet partials ---------------
        {
            float* obase = &out[(size_t)nbase * NDIMT];
#pragma unroll
            for (int t = 0; t < GPT; ++t) {
                unsigned int e = tid + TPB * t;
                unsigned int r = ge_r[t];
                unsigned int j = e - r * 48u;
                obase[ge_a[t]] = sm[SO_V + j * RST + r];
            }
            if (tid < ROWS_IT) {
                float s = 0.f;
#pragma unroll
                for (int g = 0; g < 12; ++g) s += sm[SO_LJ + g * 256 + tid];
                g_lj[(size_t)k * NSAMP + nbase + tid] = s;
            }
        }
    }
}

// ---------------------------------------------------------------------------
// Kernel 4: deterministic logdet reduction.
// ---------------------------------------------------------------------------
__global__ void reduce_lj(float* __restrict__ logj) {
    int n = blockIdx.x * blockDim.x + threadIdx.x;
    if (n >= NSAMP) return;
    float s = 0.f;
#pragma unroll
    for (int k = 0; k < NKER; ++k) s += g_lj[(size_t)k * NSAMP + n];
    logj[n] = s;
}

// ---------------------------------------------------------------------------
// Launch
// ---------------------------------------------------------------------------
extern "C" void kernel_launch(void* const* d_in, const int* in_sizes, int n_in,
                              void* d_out, int out_size) {
    const float* data     = (const float*)d_in[0];
    const float* A_raw    = (const float*)d_in[1];
    const float* x0       = (const float*)d_in[2];
    const float* logdx    = (const float*)d_in[3];
    const float* y0       = (const float*)d_in[4];
    const float* logdy    = (const float*)d_in[5];
    const float* logderiv = (const float*)d_in[6];

    float* out  = (float*)d_out;
    float* logj = out + (size_t)NSAMP * NDIMT;

    cudaFuncSetAttribute(fused_kernel,
                         cudaFuncAttributeMaxDynamicSharedMemorySize, SMEM_BYTES);

    orth_kernel<<<NKER, 64>>>(A_raw);
    knots_kernel<<<NTRT / 4, 128>>>(x0, logdx, y0, logdy, logderiv);
    lut_kernel<<<NTRT / 8, 256>>>();
    fused_kernel<<<dim3(NKER, 16), TPB, SMEM_BYTES>>>(data, out);
    reduce_lj<<<(NSAMP + 255) / 256, 256>>>(logj);
}